// round 1
// baseline (speedup 1.0000x reference)
#include <cuda_runtime.h>
#include <math.h>

// Problem dims (fixed by reference)
#define B_ 4
#define L_ 16384
#define C_ 256
#define H_ 8
#define D_ 32
#define W_ 64
#define NW_ 256
#define M_ 65536     // B_*L_
#define SHIFT_ 32
#define LMASK 16383  // L_-1

// ---------------- scratch (allocation-free: device globals) ----------------
__device__ float g_qkv [(size_t)M_ * 768];   // shifted-x @ w_qkv
__device__ float g_attn[(size_t)M_ * 256];   // attention out, scrambled-merge layout
__device__ float g_x2  [(size_t)M_ * 256];   // proj out, reverse-shifted (residual base)
__device__ float g_ln  [(size_t)M_ * 256];   // layernorm out
__device__ float g_mlp [(size_t)M_ * 1024];  // gelu(mlp1)

// ---------------- generic 128x128x8 fp32 GEMM with fused epilogues ----------
enum { MODE_QKV = 0, MODE_PROJ = 1, MODE_MLP1 = 2, MODE_MLP2 = 3 };

__device__ __forceinline__ float gelu_exact(float v) {
    return 0.5f * v * (1.0f + erff(v * 0.70710678118654752440f));
}

template <int MODE>
__global__ __launch_bounds__(256)
void sgemm_kernel(const float* __restrict__ A, const float* __restrict__ Bw,
                  const float* __restrict__ bias, const float* __restrict__ resid,
                  float* __restrict__ Cm, int N, int K) {
    __shared__ __align__(16) float As[8][128];
    __shared__ __align__(16) float Bs[8][128];

    const int bm = blockIdx.y * 128;
    const int bn = blockIdx.x * 128;
    const int tid = threadIdx.x;
    const int tx = tid & 15;        // 0..15 -> col group
    const int ty = tid >> 4;        // 0..15 -> row group

    // A tile load mapping: thread -> (row 0..127, col4 {0,4})
    const int a_row = tid >> 1;
    const int a_col = (tid & 1) * 4;
    // B tile load mapping: thread -> (row 0..7, col4 0..124)
    const int b_row = tid >> 5;
    const int b_col = (tid & 31) * 4;

    // source row of A (QKV mode gathers the cyclic shift)
    int gm = bm + a_row;
    size_t a_off;
    if (MODE == MODE_QKV) {
        int l = gm & LMASK;
        int src = (l + SHIFT_) & LMASK;
        a_off = (size_t)((gm & ~LMASK) | src) * (size_t)K;
    } else {
        a_off = (size_t)gm * (size_t)K;
    }

    float acc[8][8];
#pragma unroll
    for (int i = 0; i < 8; i++)
#pragma unroll
        for (int j = 0; j < 8; j++) acc[i][j] = 0.0f;

    for (int k0 = 0; k0 < K; k0 += 8) {
        float4 av = *(const float4*)(A + a_off + k0 + a_col);
        float4 bv = *(const float4*)(Bw + (size_t)(k0 + b_row) * N + bn + b_col);
        As[a_col + 0][a_row] = av.x;
        As[a_col + 1][a_row] = av.y;
        As[a_col + 2][a_row] = av.z;
        As[a_col + 3][a_row] = av.w;
        *(float4*)(&Bs[b_row][b_col]) = bv;
        __syncthreads();

#pragma unroll
        for (int k = 0; k < 8; k++) {
            float4 a0 = *(const float4*)(&As[k][ty * 8]);
            float4 a1 = *(const float4*)(&As[k][ty * 8 + 4]);
            float4 b0 = *(const float4*)(&Bs[k][tx * 8]);
            float4 b1 = *(const float4*)(&Bs[k][tx * 8 + 4]);
            float ar[8] = {a0.x, a0.y, a0.z, a0.w, a1.x, a1.y, a1.z, a1.w};
            float br[8] = {b0.x, b0.y, b0.z, b0.w, b1.x, b1.y, b1.z, b1.w};
#pragma unroll
            for (int i = 0; i < 8; i++)
#pragma unroll
                for (int j = 0; j < 8; j++) acc[i][j] += ar[i] * br[j];
        }
        __syncthreads();
    }

    // epilogue
#pragma unroll
    for (int ii = 0; ii < 8; ii++) {
        int gr = bm + ty * 8 + ii;
        size_t orow;
        if (MODE == MODE_PROJ) {
            // reverse cyclic shift: merged row l -> x2 row (l+SHIFT)%L
            int l = gr & LMASK;
            orow = (size_t)((gr & ~LMASK) | ((l + SHIFT_) & LMASK));
        } else {
            orow = (size_t)gr;
        }
        int col = bn + tx * 8;
        float v[8];
#pragma unroll
        for (int jj = 0; jj < 8; jj++) {
            float val = acc[ii][jj];
            if (MODE != MODE_QKV) val += bias[col + jj];
            if (MODE == MODE_MLP1) val = gelu_exact(val);
            v[jj] = val;
        }
        if (MODE == MODE_MLP2) {
            const float* rp = resid + orow * (size_t)N + col;
            float4 r0 = *(const float4*)(rp);
            float4 r1 = *(const float4*)(rp + 4);
            v[0] += r0.x; v[1] += r0.y; v[2] += r0.z; v[3] += r0.w;
            v[4] += r1.x; v[5] += r1.y; v[6] += r1.z; v[7] += r1.w;
        }
        float* cp = Cm + orow * (size_t)N + col;
        *(float4*)(cp)     = make_float4(v[0], v[1], v[2], v[3]);
        *(float4*)(cp + 4) = make_float4(v[4], v[5], v[6], v[7]);
    }
}

// ---------------- windowed attention --------------------------------------
// One block = (b, window n, head h); 64 threads, thread w owns query row w.
// Writes directly into the reference's "faithful reshape" scrambled layout:
//   row' = (h*32 + n/8)*64 + (n%8)*8 + w/8 ,  col' = (w%8)*32 + j
__global__ __launch_bounds__(64)
void attn_kernel(const float* __restrict__ qkv, float* __restrict__ attn_out) {
    const int idx = blockIdx.x;
    const int h = idx & 7;
    const int n = (idx >> 3) & 255;
    const int b = idx >> 11;
    const int tid = threadIdx.x;  // query row w

    __shared__ __align__(16) float Ks[64 * 32];
    __shared__ __align__(16) float Vs[64 * 32];

    const float* base = qkv + ((size_t)(b * L_ + n * W_)) * 768 + h * 32;

    // cooperative load of K and V tiles [64 x 32]
    for (int i = tid; i < 64 * 32; i += 64) {
        int w = i >> 5, j = i & 31;
        Ks[i] = base[(size_t)w * 768 + 256 + j];
        Vs[i] = base[(size_t)w * 768 + 512 + j];
    }
    __syncthreads();

    // q row in registers
    float q[32];
    const float* qp = base + (size_t)tid * 768;
#pragma unroll
    for (int j = 0; j < 32; j++) q[j] = qp[j];

    const float scale = 0.17677669529663688f;  // 32^-0.5
    float s[64];
#pragma unroll
    for (int w2 = 0; w2 < 64; w2++) {
        float a = 0.0f;
#pragma unroll
        for (int j = 0; j < 32; j++) a += q[j] * Ks[w2 * 32 + j];
        s[w2] = a * scale;
    }
    float mx = -1e30f;
#pragma unroll
    for (int w2 = 0; w2 < 64; w2++) mx = fmaxf(mx, s[w2]);
    float sum = 0.0f;
#pragma unroll
    for (int w2 = 0; w2 < 64; w2++) { s[w2] = __expf(s[w2] - mx); sum += s[w2]; }
    const float inv = 1.0f / sum;

    float o[32];
#pragma unroll
    for (int j = 0; j < 32; j++) o[j] = 0.0f;
#pragma unroll
    for (int w2 = 0; w2 < 64; w2++) {
        float p = s[w2] * inv;
#pragma unroll
        for (int j = 0; j < 32; j++) o[j] += p * Vs[w2 * 32 + j];
    }

    // scrambled-merge scatter
    const int drow = (h * 32 + (n >> 3)) * 64 + (n & 7) * 8 + (tid >> 3);
    const int dcol = (tid & 7) * 32;
    float* op = attn_out + ((size_t)b * L_ + drow) * 256 + dcol;
#pragma unroll
    for (int j = 0; j < 32; j += 4)
        *(float4*)(op + j) = make_float4(o[j], o[j + 1], o[j + 2], o[j + 3]);
}

// ---------------- layernorm (one warp per row of 256) ----------------------
__global__ __launch_bounds__(256)
void ln_kernel(const float* __restrict__ x2, float* __restrict__ lnout,
               const float* __restrict__ gamma, const float* __restrict__ beta) {
    const int gwarp = (blockIdx.x * 256 + threadIdx.x) >> 5;
    const int lane = threadIdx.x & 31;
    const float* xr = x2 + (size_t)gwarp * 256 + lane * 8;
    float4 v0 = *(const float4*)(xr);
    float4 v1 = *(const float4*)(xr + 4);
    float s  = v0.x + v0.y + v0.z + v0.w + v1.x + v1.y + v1.z + v1.w;
    float ss = v0.x*v0.x + v0.y*v0.y + v0.z*v0.z + v0.w*v0.w
             + v1.x*v1.x + v1.y*v1.y + v1.z*v1.z + v1.w*v1.w;
#pragma unroll
    for (int o = 16; o > 0; o >>= 1) {
        s  += __shfl_xor_sync(0xFFFFFFFFu, s,  o);
        ss += __shfl_xor_sync(0xFFFFFFFFu, ss, o);
    }
    const float mu = s * (1.0f / 256.0f);
    const float var = ss * (1.0f / 256.0f) - mu * mu;
    const float rstd = rsqrtf(var + 1e-5f);

    const float* gp = gamma + lane * 8;
    const float* bp = beta + lane * 8;
    float4 g0 = *(const float4*)(gp),  g1 = *(const float4*)(gp + 4);
    float4 b0 = *(const float4*)(bp),  b1 = *(const float4*)(bp + 4);
    float* op = lnout + (size_t)gwarp * 256 + lane * 8;
    float4 o0, o1;
    o0.x = (v0.x - mu) * rstd * g0.x + b0.x;
    o0.y = (v0.y - mu) * rstd * g0.y + b0.y;
    o0.z = (v0.z - mu) * rstd * g0.z + b0.z;
    o0.w = (v0.w - mu) * rstd * g0.w + b0.w;
    o1.x = (v1.x - mu) * rstd * g1.x + b1.x;
    o1.y = (v1.y - mu) * rstd * g1.y + b1.y;
    o1.z = (v1.z - mu) * rstd * g1.z + b1.z;
    o1.w = (v1.w - mu) * rstd * g1.w + b1.w;
    *(float4*)(op)     = o0;
    *(float4*)(op + 4) = o1;
}

// ---------------- launch ----------------------------------------------------
extern "C" void kernel_launch(void* const* d_in, const int* in_sizes, int n_in,
                              void* d_out, int out_size) {
    const float* x      = (const float*)d_in[0];
    const float* w_qkv  = (const float*)d_in[1];
    const float* w_proj = (const float*)d_in[2];
    const float* b_proj = (const float*)d_in[3];
    const float* gamma2 = (const float*)d_in[4];
    const float* beta2  = (const float*)d_in[5];
    const float* w_mlp1 = (const float*)d_in[6];
    const float* b_mlp1 = (const float*)d_in[7];
    const float* w_mlp2 = (const float*)d_in[8];
    const float* b_mlp2 = (const float*)d_in[9];
    float* out = (float*)d_out;

    float *qkv, *attn, *x2, *ln, *mlp;
    cudaGetSymbolAddress((void**)&qkv,  g_qkv);
    cudaGetSymbolAddress((void**)&attn, g_attn);
    cudaGetSymbolAddress((void**)&x2,   g_x2);
    cudaGetSymbolAddress((void**)&ln,   g_ln);
    cudaGetSymbolAddress((void**)&mlp,  g_mlp);

    // 1) QKV = shift(x) @ w_qkv          [65536 x 768]
    sgemm_kernel<MODE_QKV><<<dim3(768 / 128, M_ / 128), 256>>>(
        x, w_qkv, nullptr, nullptr, qkv, 768, 256);

    // 2) windowed attention -> scrambled merge layout
    attn_kernel<<<B_ * NW_ * H_, 64>>>(qkv, attn);

    // 3) proj + bias, scatter reverse shift -> x2
    sgemm_kernel<MODE_PROJ><<<dim3(256 / 128, M_ / 128), 256>>>(
        attn, w_proj, b_proj, nullptr, x2, 256, 256);

    // 4) layernorm
    ln_kernel<<<M_ / 8, 256>>>(x2, ln, gamma2, beta2);

    // 5) mlp1 + bias + exact GELU
    sgemm_kernel<MODE_MLP1><<<dim3(1024 / 128, M_ / 128), 256>>>(
        ln, w_mlp1, b_mlp1, nullptr, mlp, 1024, 256);

    // 6) mlp2 + bias + residual(x2) -> d_out
    sgemm_kernel<MODE_MLP2><<<dim3(256 / 128, M_ / 128), 256>>>(
        mlp, w_mlp2, b_mlp2, x2, out, 256, 1024);
}

// round 3
// speedup vs baseline: 2.1435x; 2.1435x over previous
#include <cuda_runtime.h>
#include <cuda_bf16.h>
#include <math.h>
#include <stdint.h>

#define B_ 4
#define L_ 16384
#define M_ 65536
#define SHIFT_ 32
#define LMASK 16383

// ---------------- scratch (allocation-free device globals) ------------------
__device__ __nv_bfloat16 g_xhi[(size_t)M_ * 256], g_xlo[(size_t)M_ * 256];
__device__ float        g_qkv[(size_t)M_ * 768];
__device__ __nv_bfloat16 g_ahi[(size_t)M_ * 256], g_alo[(size_t)M_ * 256];
__device__ float        g_x2 [(size_t)M_ * 256];
__device__ __nv_bfloat16 g_lhi[(size_t)M_ * 256], g_llo[(size_t)M_ * 256];
__device__ __nv_bfloat16 g_mhi[(size_t)M_ * 1024], g_mlo[(size_t)M_ * 1024];
__device__ __nv_bfloat16 g_wq_hi[768 * 256],  g_wq_lo[768 * 256];
__device__ __nv_bfloat16 g_wp_hi[256 * 256],  g_wp_lo[256 * 256];
__device__ __nv_bfloat16 g_w1_hi[1024 * 256], g_w1_lo[1024 * 256];
__device__ __nv_bfloat16 g_w2_hi[256 * 1024], g_w2_lo[256 * 1024];

// ---------------- small helpers --------------------------------------------
__device__ __forceinline__ uint32_t smem_to_u32(const void* p) {
    uint32_t a;
    asm("{ .reg .u64 t; cvta.to.shared.u64 t, %1; cvt.u32.u64 %0, t; }" : "=r"(a) : "l"(p));
    return a;
}
__device__ __forceinline__ void split_f(float v, float& hi, float& lo) {
    __nv_bfloat16 h = __float2bfloat16(v);
    hi = __bfloat162float(h);
    lo = v - hi;
}
__device__ __forceinline__ unsigned pack2(float a, float b) {
    return (unsigned)__bfloat16_as_ushort(__float2bfloat16(a)) |
           ((unsigned)__bfloat16_as_ushort(__float2bfloat16(b)) << 16);
}
__device__ __forceinline__ float gelu_exact(float v) {
    return 0.5f * v * (1.0f + erff(v * 0.70710678118654752440f));
}

#define CP16(dst, src) \
    asm volatile("cp.async.cg.shared.global [%0], [%1], 16;" :: "r"(dst), "l"(src))
#define CP_COMMIT() asm volatile("cp.async.commit_group;")
#define CP_WAIT1() asm volatile("cp.async.wait_group 1;")
#define CP_WAIT0() asm volatile("cp.async.wait_group 0;")
#define LDSM4(r0, r1, r2, r3, addr) \
    asm volatile("ldmatrix.sync.aligned.m8n8.x4.shared.b16 {%0,%1,%2,%3}, [%4];" \
                 : "=r"(r0), "=r"(r1), "=r"(r2), "=r"(r3) : "r"(addr))

__device__ __forceinline__ void mma16816(float* d, const uint32_t* a, const uint32_t* b) {
    asm volatile(
        "mma.sync.aligned.m16n8k16.row.col.f32.bf16.bf16.f32 "
        "{%0,%1,%2,%3}, {%4,%5,%6,%7}, {%8,%9}, {%0,%1,%2,%3};"
        : "+f"(d[0]), "+f"(d[1]), "+f"(d[2]), "+f"(d[3])
        : "r"(a[0]), "r"(a[1]), "r"(a[2]), "r"(a[3]), "r"(b[0]), "r"(b[1]));
}

// ---------------- prep kernels ---------------------------------------------
__global__ __launch_bounds__(256)
void prep_x(const float* __restrict__ x, __nv_bfloat16* __restrict__ xhi,
            __nv_bfloat16* __restrict__ xlo) {
    int idx = blockIdx.x * 256 + threadIdx.x;
    int m = idx >> 5, c = (idx & 31) * 8;
    int l = m & LMASK;
    int src = (m & ~LMASK) | ((l + SHIFT_) & LMASK);
    const float* xp = x + (size_t)src * 256 + c;
    float4 v0 = *(const float4*)xp;
    float4 v1 = *(const float4*)(xp + 4);
    float vv[8] = {v0.x, v0.y, v0.z, v0.w, v1.x, v1.y, v1.z, v1.w};
    float h[8], lo[8];
#pragma unroll
    for (int i = 0; i < 8; i++) split_f(vv[i], h[i], lo[i]);
    uint4 hv = make_uint4(pack2(h[0], h[1]), pack2(h[2], h[3]), pack2(h[4], h[5]), pack2(h[6], h[7]));
    uint4 lv = make_uint4(pack2(lo[0], lo[1]), pack2(lo[2], lo[3]), pack2(lo[4], lo[5]), pack2(lo[6], lo[7]));
    *(uint4*)(xhi + (size_t)m * 256 + c) = hv;
    *(uint4*)(xlo + (size_t)m * 256 + c) = lv;
}

__global__ __launch_bounds__(256)
void prep_wt(const float* __restrict__ w, __nv_bfloat16* __restrict__ hi,
             __nv_bfloat16* __restrict__ lo, int K, int N) {
    int idx = blockIdx.x * 256 + threadIdx.x;
    int n = idx / K, k = idx % K;
    float v = w[(size_t)k * N + n];
    float h, l2;
    split_f(v, h, l2);
    hi[idx] = __float2bfloat16(h);
    lo[idx] = __float2bfloat16(l2);
}

// ---------------- HMMA split-bf16 GEMM --------------------------------------
// C[M,N] = A[M,K] @ WT[N,K]^T; A,WT are bf16 (hi,lo) pairs; fp32 accumulate.
// MODE: 0=QKV(f32 out), 1=PROJ(bias + reverse-shift scatter, f32),
//       2=MLP1(bias+gelu, bf16 hi/lo out), 3=MLP2(bias+resid, f32 out)
#define BKB 64          // bytes of K per tile row (32 bf16)
#define RSTRIDE 80      // padded smem row stride (bytes)
#define ARR 10240       // 128 * 80
#define STAGE 40960     // 4 arrays per stage
#define SMEM_SZ 81920   // 2 stages

template <int MODE>
__global__ __launch_bounds__(256)
void hmma_gemm(const __nv_bfloat16* __restrict__ Ahi, const __nv_bfloat16* __restrict__ Alo,
               const __nv_bfloat16* __restrict__ Bhi, const __nv_bfloat16* __restrict__ Blo,
               const float* __restrict__ bias, const float* __restrict__ resid,
               float* __restrict__ Of32, __nv_bfloat16* __restrict__ Ohi,
               __nv_bfloat16* __restrict__ Olo, int N, int K, int NT) {
    extern __shared__ char smem[];
    const uint32_t su = smem_to_u32(smem);
    const int tid = threadIdx.x;
    const int wid = tid >> 5;
    const int lane = tid & 31;
    const int warp_m = wid & 3;     // 4 M bands of 32
    const int warp_n = wid >> 2;    // 2 N bands of 64
    const int bm = blockIdx.y * 128;
    const int bn = blockIdx.x * 128;

    // cp.async stage loader: 4 arrays x 128 rows x 4 chunks(16B)
    const int ld_row = tid >> 2;    // 0..63
    const int ld_ch = tid & 3;
    auto issue_stage = [&](int s, int kt) {
        const uint32_t base = su + s * STAGE;
        const size_t kb = (size_t)kt * 32 + ld_ch * 8;
#pragma unroll
        for (int rep = 0; rep < 2; rep++) {
            const int r = ld_row + rep * 64;
            const size_t ga = (size_t)(bm + r) * K + kb;
            const size_t gb = (size_t)(bn + r) * K + kb;
            const uint32_t ds = (uint32_t)(r * RSTRIDE + ld_ch * 16);
            CP16(base + ds,            Ahi + ga);
            CP16(base + ARR + ds,      Alo + ga);
            CP16(base + 2 * ARR + ds,  Bhi + gb);
            CP16(base + 3 * ARR + ds,  Blo + gb);
        }
        CP_COMMIT();
    };

    float acc[2][8][4];
#pragma unroll
    for (int mt = 0; mt < 2; mt++)
#pragma unroll
        for (int nt = 0; nt < 8; nt++)
#pragma unroll
            for (int j = 0; j < 4; j++) acc[mt][nt][j] = 0.0f;

    issue_stage(0, 0);
    if (NT > 1) issue_stage(1, 1);

    // fragment addressing
    const int arow = warp_m * 32 + (lane & 15);
    const uint32_t abyte = (uint32_t)((lane >> 4) * 16);
    const int brow = warp_n * 64 + (lane & 7) + ((lane >> 4) << 3);
    const uint32_t bbyte = (uint32_t)(((lane >> 3) & 1) * 16);

    for (int kt = 0; kt < NT; kt++) {
        if (kt < NT - 1) { CP_WAIT1(); } else { CP_WAIT0(); }
        __syncthreads();
        const uint32_t ab = su + (kt & 1) * STAGE;

#pragma unroll
        for (int s2 = 0; s2 < 2; s2++) {
            const uint32_t koff = s2 * 32;
            uint32_t a_hi[2][4], a_lo[2][4];
#pragma unroll
            for (int mt = 0; mt < 2; mt++) {
                uint32_t ad = ab + (uint32_t)((arow + mt * 16) * RSTRIDE) + koff + abyte;
                LDSM4(a_hi[mt][0], a_hi[mt][1], a_hi[mt][2], a_hi[mt][3], ad);
                LDSM4(a_lo[mt][0], a_lo[mt][1], a_lo[mt][2], a_lo[mt][3], ad + ARR);
            }
            uint32_t b_hi[8][2], b_lo[8][2];
#pragma unroll
            for (int g = 0; g < 4; g++) {
                uint32_t bd = ab + 2 * ARR + (uint32_t)((brow + g * 16) * RSTRIDE) + koff + bbyte;
                LDSM4(b_hi[2 * g][0], b_hi[2 * g][1], b_hi[2 * g + 1][0], b_hi[2 * g + 1][1], bd);
                LDSM4(b_lo[2 * g][0], b_lo[2 * g][1], b_lo[2 * g + 1][0], b_lo[2 * g + 1][1], bd + ARR);
            }
#pragma unroll
            for (int mt = 0; mt < 2; mt++)
#pragma unroll
                for (int nt = 0; nt < 8; nt++) {
                    mma16816(acc[mt][nt], a_hi[mt], b_hi[nt]);
                    mma16816(acc[mt][nt], a_lo[mt], b_hi[nt]);
                    mma16816(acc[mt][nt], a_hi[mt], b_lo[nt]);
                }
        }
        __syncthreads();
        if (kt + 2 < NT) issue_stage(kt & 1, kt + 2);
    }

    // ---- epilogue ----------------------------------------------------------
    const int lr = lane >> 2;            // 0..7
    const int lc = (lane & 3) * 2;
#pragma unroll
    for (int mt = 0; mt < 2; mt++) {
        const int mrow0 = bm + warp_m * 32 + mt * 16 + lr;
#pragma unroll
        for (int half = 0; half < 2; half++) {
            const int m = mrow0 + half * 8;
            int orow = m;
            if (MODE == 1) { int l = m & LMASK; orow = (m & ~LMASK) | ((l + SHIFT_) & LMASK); }
#pragma unroll
            for (int nt = 0; nt < 8; nt++) {
                const int c = bn + warp_n * 64 + nt * 8 + lc;
                float v0 = acc[mt][nt][half * 2 + 0];
                float v1 = acc[mt][nt][half * 2 + 1];
                if (MODE != 0) { v0 += __ldg(&bias[c]); v1 += __ldg(&bias[c + 1]); }
                if (MODE == 2) { v0 = gelu_exact(v0); v1 = gelu_exact(v1); }
                if (MODE == 3) {
                    float2 rr = *(const float2*)(resid + (size_t)m * N + c);
                    v0 += rr.x; v1 += rr.y;
                }
                if (MODE == 2) {
                    float h0, l0, h1, l1;
                    split_f(v0, h0, l0); split_f(v1, h1, l1);
                    *(uint32_t*)(Ohi + (size_t)m * N + c) = pack2(h0, h1);
                    *(uint32_t*)(Olo + (size_t)m * N + c) = pack2(l0, l1);
                } else {
                    *(float2*)(Of32 + (size_t)orow * N + c) = make_float2(v0, v1);
                }
            }
        }
    }
}

// ---------------- windowed attention (fp32, split bf16 out) -----------------
__global__ __launch_bounds__(64)
void attn_kernel(const float* __restrict__ qkv, __nv_bfloat16* __restrict__ ahi,
                 __nv_bfloat16* __restrict__ alo) {
    const int idx = blockIdx.x;
    const int h = idx & 7;
    const int n = (idx >> 3) & 255;
    const int b = idx >> 11;
    const int tid = threadIdx.x;

    __shared__ __align__(16) float Ks[64 * 32];
    __shared__ __align__(16) float Vs[64 * 32];

    const float* base = qkv + ((size_t)(b * L_ + n * 64)) * 768 + h * 32;
    for (int i = tid; i < 64 * 32; i += 64) {
        int w = i >> 5, j = i & 31;
        Ks[i] = base[(size_t)w * 768 + 256 + j];
        Vs[i] = base[(size_t)w * 768 + 512 + j];
    }
    __syncthreads();

    float q[32];
    const float* qp = base + (size_t)tid * 768;
#pragma unroll
    for (int j = 0; j < 32; j++) q[j] = qp[j];

    const float scale = 0.17677669529663688f;
    float s[64];
#pragma unroll
    for (int w2 = 0; w2 < 64; w2++) {
        float a = 0.0f;
#pragma unroll
        for (int j = 0; j < 32; j++) a += q[j] * Ks[w2 * 32 + j];
        s[w2] = a * scale;
    }
    float mx = -1e30f;
#pragma unroll
    for (int w2 = 0; w2 < 64; w2++) mx = fmaxf(mx, s[w2]);
    float sum = 0.0f;
#pragma unroll
    for (int w2 = 0; w2 < 64; w2++) { s[w2] = __expf(s[w2] - mx); sum += s[w2]; }
    const float inv = 1.0f / sum;

    float o[32];
#pragma unroll
    for (int j = 0; j < 32; j++) o[j] = 0.0f;
#pragma unroll
    for (int w2 = 0; w2 < 64; w2++) {
        float p = s[w2] * inv;
#pragma unroll
        for (int j = 0; j < 32; j++) o[j] += p * Vs[w2 * 32 + j];
    }

    const int drow = (h * 32 + (n >> 3)) * 64 + (n & 7) * 8 + (tid >> 3);
    const int dcol = (tid & 7) * 32;
    const size_t obase = ((size_t)b * L_ + drow) * 256 + dcol;
#pragma unroll
    for (int g = 0; g < 4; g++) {
        float hh[8], ll[8];
#pragma unroll
        for (int t = 0; t < 8; t++) split_f(o[g * 8 + t], hh[t], ll[t]);
        uint4 hv = make_uint4(pack2(hh[0], hh[1]), pack2(hh[2], hh[3]),
                              pack2(hh[4], hh[5]), pack2(hh[6], hh[7]));
        uint4 lv = make_uint4(pack2(ll[0], ll[1]), pack2(ll[2], ll[3]),
                              pack2(ll[4], ll[5]), pack2(ll[6], ll[7]));
        *(uint4*)(ahi + obase + g * 8) = hv;
        *(uint4*)(alo + obase + g * 8) = lv;
    }
}

// ---------------- layernorm (split bf16 out) --------------------------------
__global__ __launch_bounds__(256)
void ln_kernel(const float* __restrict__ x2, __nv_bfloat16* __restrict__ lhi,
               __nv_bfloat16* __restrict__ llo, const float* __restrict__ gamma,
               const float* __restrict__ beta) {
    const int gwarp = (blockIdx.x * 256 + threadIdx.x) >> 5;
    const int lane = threadIdx.x & 31;
    const float* xr = x2 + (size_t)gwarp * 256 + lane * 8;
    float4 v0 = *(const float4*)(xr);
    float4 v1 = *(const float4*)(xr + 4);
    float s = v0.x + v0.y + v0.z + v0.w + v1.x + v1.y + v1.z + v1.w;
    float ss = v0.x * v0.x + v0.y * v0.y + v0.z * v0.z + v0.w * v0.w +
               v1.x * v1.x + v1.y * v1.y + v1.z * v1.z + v1.w * v1.w;
#pragma unroll
    for (int o = 16; o > 0; o >>= 1) {
        s += __shfl_xor_sync(0xFFFFFFFFu, s, o);
        ss += __shfl_xor_sync(0xFFFFFFFFu, ss, o);
    }
    const float mu = s * (1.0f / 256.0f);
    const float var = ss * (1.0f / 256.0f) - mu * mu;
    const float rstd = rsqrtf(var + 1e-5f);

    const float* gp = gamma + lane * 8;
    const float* bp = beta + lane * 8;
    float4 g0 = *(const float4*)(gp), g1 = *(const float4*)(gp + 4);
    float4 b0 = *(const float4*)(bp), b1 = *(const float4*)(bp + 4);
    float o8[8];
    o8[0] = (v0.x - mu) * rstd * g0.x + b0.x;
    o8[1] = (v0.y - mu) * rstd * g0.y + b0.y;
    o8[2] = (v0.z - mu) * rstd * g0.z + b0.z;
    o8[3] = (v0.w - mu) * rstd * g0.w + b0.w;
    o8[4] = (v1.x - mu) * rstd * g1.x + b1.x;
    o8[5] = (v1.y - mu) * rstd * g1.y + b1.y;
    o8[6] = (v1.z - mu) * rstd * g1.z + b1.z;
    o8[7] = (v1.w - mu) * rstd * g1.w + b1.w;
    float h[8], l2[8];
#pragma unroll
    for (int i = 0; i < 8; i++) split_f(o8[i], h[i], l2[i]);
    uint4 hv = make_uint4(pack2(h[0], h[1]), pack2(h[2], h[3]), pack2(h[4], h[5]), pack2(h[6], h[7]));
    uint4 lv = make_uint4(pack2(l2[0], l2[1]), pack2(l2[2], l2[3]), pack2(l2[4], l2[5]), pack2(l2[6], l2[7]));
    *(uint4*)(lhi + (size_t)gwarp * 256 + lane * 8) = hv;
    *(uint4*)(llo + (size_t)gwarp * 256 + lane * 8) = lv;
}

// ---------------- launch ----------------------------------------------------
extern "C" void kernel_launch(void* const* d_in, const int* in_sizes, int n_in,
                              void* d_out, int out_size) {
    const float* x      = (const float*)d_in[0];
    const float* w_qkv  = (const float*)d_in[1];
    const float* w_proj = (const float*)d_in[2];
    const float* b_proj = (const float*)d_in[3];
    const float* gamma2 = (const float*)d_in[4];
    const float* beta2  = (const float*)d_in[5];
    const float* w_mlp1 = (const float*)d_in[6];
    const float* b_mlp1 = (const float*)d_in[7];
    const float* w_mlp2 = (const float*)d_in[8];
    const float* b_mlp2 = (const float*)d_in[9];
    float* out = (float*)d_out;

    __nv_bfloat16 *xhi, *xlo, *ahi, *alo, *lhi, *llo, *mhi, *mlo;
    __nv_bfloat16 *wqh, *wql, *wph, *wpl, *w1h, *w1l, *w2h, *w2l;
    float *qkv, *x2;
    cudaGetSymbolAddress((void**)&xhi, g_xhi);  cudaGetSymbolAddress((void**)&xlo, g_xlo);
    cudaGetSymbolAddress((void**)&qkv, g_qkv);
    cudaGetSymbolAddress((void**)&ahi, g_ahi);  cudaGetSymbolAddress((void**)&alo, g_alo);
    cudaGetSymbolAddress((void**)&x2, g_x2);
    cudaGetSymbolAddress((void**)&lhi, g_lhi);  cudaGetSymbolAddress((void**)&llo, g_llo);
    cudaGetSymbolAddress((void**)&mhi, g_mhi);  cudaGetSymbolAddress((void**)&mlo, g_mlo);
    cudaGetSymbolAddress((void**)&wqh, g_wq_hi); cudaGetSymbolAddress((void**)&wql, g_wq_lo);
    cudaGetSymbolAddress((void**)&wph, g_wp_hi); cudaGetSymbolAddress((void**)&wpl, g_wp_lo);
    cudaGetSymbolAddress((void**)&w1h, g_w1_hi); cudaGetSymbolAddress((void**)&w1l, g_w1_lo);
    cudaGetSymbolAddress((void**)&w2h, g_w2_hi); cudaGetSymbolAddress((void**)&w2l, g_w2_lo);

    cudaFuncSetAttribute(hmma_gemm<0>, cudaFuncAttributeMaxDynamicSharedMemorySize, SMEM_SZ);
    cudaFuncSetAttribute(hmma_gemm<1>, cudaFuncAttributeMaxDynamicSharedMemorySize, SMEM_SZ);
    cudaFuncSetAttribute(hmma_gemm<2>, cudaFuncAttributeMaxDynamicSharedMemorySize, SMEM_SZ);
    cudaFuncSetAttribute(hmma_gemm<3>, cudaFuncAttributeMaxDynamicSharedMemorySize, SMEM_SZ);

    // prep: shift+split x, transpose+split weights
    prep_x<<<M_ * 32 / 256, 256>>>(x, xhi, xlo);
    prep_wt<<<768 * 256 / 256, 256>>>(w_qkv, wqh, wql, 256, 768);
    prep_wt<<<256 * 256 / 256, 256>>>(w_proj, wph, wpl, 256, 256);
    prep_wt<<<1024 * 256 / 256, 256>>>(w_mlp1, w1h, w1l, 256, 1024);
    prep_wt<<<256 * 1024 / 256, 256>>>(w_mlp2, w2h, w2l, 1024, 256);

    // 1) QKV: [65536 x 768] = xsplit @ wqkvT
    hmma_gemm<0><<<dim3(6, 512), 256, SMEM_SZ>>>(xhi, xlo, wqh, wql, nullptr, nullptr,
                                                 qkv, nullptr, nullptr, 768, 256, 8);
    // 2) windowed attention
    attn_kernel<<<B_ * 256 * 8, 64>>>(qkv, ahi, alo);
    // 3) proj + bias + reverse-shift scatter
    hmma_gemm<1><<<dim3(2, 512), 256, SMEM_SZ>>>(ahi, alo, wph, wpl, b_proj, nullptr,
                                                 x2, nullptr, nullptr, 256, 256, 8);
    // 4) layernorm
    ln_kernel<<<M_ / 8, 256>>>(x2, lhi, llo, gamma2, beta2);
    // 5) mlp1 + bias + gelu -> split bf16
    hmma_gemm<2><<<dim3(8, 512), 256, SMEM_SZ>>>(lhi, llo, w1h, w1l, b_mlp1, nullptr,
                                                 nullptr, mhi, mlo, 1024, 256, 8);
    // 6) mlp2 + bias + residual -> out
    hmma_gemm<3><<<dim3(2, 512), 256, SMEM_SZ>>>(mhi, mlo, w2h, w2l, b_mlp2, x2,
                                                 out, nullptr, nullptr, 256, 1024, 32);
}